// round 1
// baseline (speedup 1.0000x reference)
#include <cuda_runtime.h>
#include <math.h>

#define BATCH 2
#define TSEQ  2048
#define NHEAD 12
#define HDIM  64
#define CEMB  768
#define C3    (3 * CEMB)

// Scratch (no allocations allowed): qkv [B, T, 3C], y [B, T, C]
__device__ float g_qkv[BATCH * TSEQ * C3];   // 36 MB
__device__ float g_y[BATCH * TSEQ * CEMB];   // 12 MB

// ---------------------------------------------------------------------------
// Generic tiled SGEMM with bias: C[m,n] = sum_k A[m,k]*B[k,n] + bias[n]
// A: [M,K] row-major, B: [K,N] row-major. M,N multiples of 128, K multiple of 8.
// 128x128 tile, BK=8, 256 threads, 8x8 per-thread microtile.
// ---------------------------------------------------------------------------
__global__ __launch_bounds__(256) void sgemm_bias(
    const float* __restrict__ A, const float* __restrict__ B,
    const float* __restrict__ bias, float* __restrict__ C,
    int N, int K) {
  __shared__ float As[8][128];
  __shared__ float Bs[8][128];

  const int tid = threadIdx.x;
  const int bm = blockIdx.y, bn = blockIdx.x;

  const int arow = tid >> 1;            // 0..127
  const int acol = (tid & 1) << 2;      // 0 or 4
  const int brow = tid >> 5;            // 0..7
  const int bcol = (tid & 31) << 2;     // 0..124

  const float* Ag = A + (size_t)(bm * 128 + arow) * K + acol;
  const float* Bg = B + (size_t)brow * N + bn * 128 + bcol;

  const int tx = tid & 15, ty = tid >> 4;

  float acc[8][8];
#pragma unroll
  for (int i = 0; i < 8; i++)
#pragma unroll
    for (int j = 0; j < 8; j++) acc[i][j] = 0.0f;

  for (int kb = 0; kb < K; kb += 8) {
    float4 a4 = *(const float4*)(Ag + kb);
    float4 b4 = *(const float4*)(Bg + (size_t)kb * N);
    As[acol + 0][arow] = a4.x;
    As[acol + 1][arow] = a4.y;
    As[acol + 2][arow] = a4.z;
    As[acol + 3][arow] = a4.w;
    *(float4*)&Bs[brow][bcol] = b4;
    __syncthreads();

#pragma unroll
    for (int k = 0; k < 8; k++) {
      float4 a0 = *(const float4*)&As[k][ty * 8];
      float4 a1 = *(const float4*)&As[k][ty * 8 + 4];
      float4 b0 = *(const float4*)&Bs[k][tx * 8];
      float4 b1 = *(const float4*)&Bs[k][tx * 8 + 4];
      float ar[8] = {a0.x, a0.y, a0.z, a0.w, a1.x, a1.y, a1.z, a1.w};
      float br[8] = {b0.x, b0.y, b0.z, b0.w, b1.x, b1.y, b1.z, b1.w};
#pragma unroll
      for (int i = 0; i < 8; i++)
#pragma unroll
        for (int j = 0; j < 8; j++) acc[i][j] += ar[i] * br[j];
    }
    __syncthreads();
  }

  const int colb = bn * 128 + tx * 8;
  float4 bias0 = *(const float4*)&bias[colb];
  float4 bias1 = *(const float4*)&bias[colb + 4];
#pragma unroll
  for (int i = 0; i < 8; i++) {
    int row = bm * 128 + ty * 8 + i;
    float* Cp = C + (size_t)row * N + colb;
    float4 c0 = make_float4(acc[i][0] + bias0.x, acc[i][1] + bias0.y,
                            acc[i][2] + bias0.z, acc[i][3] + bias0.w);
    float4 c1 = make_float4(acc[i][4] + bias1.x, acc[i][5] + bias1.y,
                            acc[i][6] + bias1.z, acc[i][7] + bias1.w);
    *(float4*)&Cp[0] = c0;
    *(float4*)&Cp[4] = c1;
  }
}

// ---------------------------------------------------------------------------
// Fused causal attention (flash-style, fp32, online softmax).
// Grid: (T/64, B*H). Block: 256 threads.
// Each CTA: one 64-query tile of one (b,h). Iterates key tiles 0..qb.
// Thread t: row r = t/4 (query within tile), col group cg = (t%4)*16.
// Smem pitch 68 floats: conflict-free for both strided-row and float4 access.
// ---------------------------------------------------------------------------
#define PITCH 68
#define ATT_SMEM (4 * 64 * PITCH * sizeof(float))  // Qs, Ks, Vs, Ps = 69632 B

__global__ __launch_bounds__(256) void attn_kernel() {
  extern __shared__ float sm[];
  float* Qs = sm;
  float* Ks = sm + 64 * PITCH;
  float* Vs = sm + 2 * 64 * PITCH;
  float* Ps = sm + 3 * 64 * PITCH;

  const int tid = threadIdx.x;
  const int qb = blockIdx.x;           // query tile 0..31
  const int bh = blockIdx.y;           // 0..23
  const int b = bh / NHEAD, h = bh % NHEAD;
  const int q0 = qb * 64;

  const int r  = tid >> 2;             // query row within tile 0..63
  const int cg = (tid & 3) << 4;       // col group base 0/16/32/48

  const float* qkv_b = g_qkv + (size_t)b * TSEQ * C3;
  const int hoff = h * HDIM;

  // Load Q tile (64 rows x 64 dims)
  for (int i = tid; i < 64 * 16; i += 256) {
    int rr = i >> 4;
    int d4 = (i & 15) << 2;
    *(float4*)&Qs[rr * PITCH + d4] =
        *(const float4*)&qkv_b[(size_t)(q0 + rr) * C3 + hoff + d4];
  }

  float m = -1e30f, l = 0.0f;
  float o[16];
#pragma unroll
  for (int j = 0; j < 16; j++) o[j] = 0.0f;

  __syncthreads();

  for (int kb = 0; kb <= qb; kb++) {
    const int k0 = kb * 64;
    // Load K and V tiles
    for (int i = tid; i < 64 * 16; i += 256) {
      int rr = i >> 4;
      int d4 = (i & 15) << 2;
      const float* base = qkv_b + (size_t)(k0 + rr) * C3 + hoff + d4;
      *(float4*)&Ks[rr * PITCH + d4] = *(const float4*)(base + CEMB);
      *(float4*)&Vs[rr * PITCH + d4] = *(const float4*)(base + 2 * CEMB);
    }
    __syncthreads();

    // S = Q K^T (scaled)
    float s[16];
#pragma unroll
    for (int j = 0; j < 16; j++) s[j] = 0.0f;
#pragma unroll
    for (int d = 0; d < 64; d += 4) {
      float4 q4 = *(const float4*)&Qs[r * PITCH + d];
#pragma unroll
      for (int j = 0; j < 16; j++) {
        float4 k4 = *(const float4*)&Ks[(cg + j) * PITCH + d];
        s[j] += q4.x * k4.x + q4.y * k4.y + q4.z * k4.z + q4.w * k4.w;
      }
    }
#pragma unroll
    for (int j = 0; j < 16; j++) s[j] *= 0.125f;   // 1/sqrt(64)

    // Causal mask on the diagonal tile
    if (kb == qb) {
#pragma unroll
      for (int j = 0; j < 16; j++)
        if (cg + j > r) s[j] = -1e30f;
    }

    // Row max (16 local + 4-lane shfl)
    float mx = s[0];
#pragma unroll
    for (int j = 1; j < 16; j++) mx = fmaxf(mx, s[j]);
    mx = fmaxf(mx, __shfl_xor_sync(0xffffffffu, mx, 1));
    mx = fmaxf(mx, __shfl_xor_sync(0xffffffffu, mx, 2));

    float m_new = fmaxf(m, mx);
    float corr = __expf(m - m_new);

    float ls = 0.0f;
#pragma unroll
    for (int j = 0; j < 16; j++) {
      float p = __expf(s[j] - m_new);
      Ps[r * PITCH + cg + j] = p;
      ls += p;
    }
    ls += __shfl_xor_sync(0xffffffffu, ls, 1);
    ls += __shfl_xor_sync(0xffffffffu, ls, 2);
    l = l * corr + ls;
    m = m_new;

#pragma unroll
    for (int j = 0; j < 16; j++) o[j] *= corr;

    __syncthreads();

    // O += P V  (thread accumulates dims cg..cg+15 of row r)
#pragma unroll 8
    for (int k = 0; k < 64; k++) {
      float pv = Ps[r * PITCH + k];
#pragma unroll
      for (int jg = 0; jg < 4; jg++) {
        float4 v4 = *(const float4*)&Vs[k * PITCH + cg + jg * 4];
        o[jg * 4 + 0] += pv * v4.x;
        o[jg * 4 + 1] += pv * v4.y;
        o[jg * 4 + 2] += pv * v4.z;
        o[jg * 4 + 3] += pv * v4.w;
      }
    }
    __syncthreads();
  }

  // Write y[b, q0+r, h*64 + cg + j] = o[j] / l
  const float inv = 1.0f / l;
  const size_t orow = (size_t)(b * TSEQ + q0 + r) * CEMB + hoff + cg;
#pragma unroll
  for (int jg = 0; jg < 4; jg++) {
    float4 v = make_float4(o[jg * 4 + 0] * inv, o[jg * 4 + 1] * inv,
                           o[jg * 4 + 2] * inv, o[jg * 4 + 3] * inv);
    *(float4*)&g_y[orow + jg * 4] = v;
  }
}

// ---------------------------------------------------------------------------
extern "C" void kernel_launch(void* const* d_in, const int* in_sizes, int n_in,
                              void* d_out, int out_size) {
  const float* x      = (const float*)d_in[0];
  const float* W_attn = (const float*)d_in[1];
  const float* b_attn = (const float*)d_in[2];
  const float* W_proj = (const float*)d_in[3];
  const float* b_proj = (const float*)d_in[4];
  float* out = (float*)d_out;

  float* qkv; cudaGetSymbolAddress((void**)&qkv, g_qkv);
  float* y;   cudaGetSymbolAddress((void**)&y,   g_y);

  const int M = BATCH * TSEQ;  // 4096

  // 1) QKV projection: [4096,768] @ [768,2304] + bias
  sgemm_bias<<<dim3(C3 / 128, M / 128), 256>>>(x, W_attn, b_attn, qkv, C3, CEMB);

  // 2) Fused causal attention
  cudaFuncSetAttribute(attn_kernel, cudaFuncAttributeMaxDynamicSharedMemorySize,
                       (int)ATT_SMEM);
  attn_kernel<<<dim3(TSEQ / 64, BATCH * NHEAD), 256, ATT_SMEM>>>();

  // 3) Output projection: [4096,768] @ [768,768] + bias
  sgemm_bias<<<dim3(CEMB / 128, M / 128), 256>>>(y, W_proj, b_proj, out, CEMB, CEMB);
}

// round 2
// speedup vs baseline: 8.2333x; 8.2333x over previous
#include <cuda_runtime.h>
#include <stdint.h>
#include <math.h>

#define BATCH 2
#define TSEQ  2048
#define NHEAD 12
#define HDIM  64
#define CEMB  768
#define C3    (3 * CEMB)

// Scratch (no allocations allowed)
__device__ float g_qkv[BATCH * TSEQ * C3];   // 36 MB
__device__ float g_y[BATCH * TSEQ * CEMB];   // 12 MB

__device__ __forceinline__ uint32_t f2tf(float x) {
  uint32_t r;
  asm("cvt.rna.tf32.f32 %0, %1;" : "=r"(r) : "f"(x));
  return r;
}
__device__ __forceinline__ float4 tf4(float4 v) {
  v.x = __uint_as_float(f2tf(v.x));
  v.y = __uint_as_float(f2tf(v.y));
  v.z = __uint_as_float(f2tf(v.z));
  v.w = __uint_as_float(f2tf(v.w));
  return v;
}
__device__ __forceinline__ uint32_t fu(float x) { return __float_as_uint(x); }

// D += A(16x8) * B(8x8), tf32 inputs, f32 accum
__device__ __forceinline__ void mma8(float* c, uint32_t a0, uint32_t a1,
                                     uint32_t a2, uint32_t a3,
                                     uint32_t b0, uint32_t b1) {
  asm volatile(
      "mma.sync.aligned.m16n8k8.row.col.f32.tf32.tf32.f32 "
      "{%0,%1,%2,%3}, {%4,%5,%6,%7}, {%8,%9}, {%0,%1,%2,%3};\n"
      : "+f"(c[0]), "+f"(c[1]), "+f"(c[2]), "+f"(c[3])
      : "r"(a0), "r"(a1), "r"(a2), "r"(a3), "r"(b0), "r"(b1));
}

// ---------------------------------------------------------------------------
// tf32 tensor-core GEMM with bias: C[m,n] = A[m,:] @ B[:,n] + bias[n]
// A [M,K] row-major, B [K,N] row-major. 128x128 tile, BK=16, 256 thr (8 warps),
// warp tile 64x32 (4 m-tiles x 4 n-tiles of m16n8k8).
// ---------------------------------------------------------------------------
#define APITCH 20    // As[128][20] words — frag banks 20r+q mod 32 all unique
#define BPITCH 132   // Bs[16][132] words — frag banks 4q+r mod 32 all unique

__global__ __launch_bounds__(256) void gemm_tf32(
    const float* __restrict__ A, const float* __restrict__ B,
    const float* __restrict__ bias, float* __restrict__ C, int N, int K) {
  __shared__ float As[128 * APITCH];
  __shared__ float Bs[16 * BPITCH];

  const int tid = threadIdx.x;
  const int warp = tid >> 5, lane = tid & 31;
  const int r = lane >> 2, q = lane & 3;
  const int wm = (warp >> 2) * 64, wn = (warp & 3) * 32;
  const int bm = blockIdx.y * 128, bn = blockIdx.x * 128;

  float acc[4][4][4];
#pragma unroll
  for (int i = 0; i < 4; i++)
#pragma unroll
    for (int j = 0; j < 4; j++)
#pragma unroll
      for (int t = 0; t < 4; t++) acc[i][j][t] = 0.0f;

  for (int kb = 0; kb < K; kb += 16) {
    // Stage A (128x16) and B (16x128), rounding to tf32 at store
#pragma unroll
    for (int i = 0; i < 2; i++) {
      int idx = tid + i * 256;
      int row = idx >> 2, c4 = (idx & 3) * 4;
      float4 v = *(const float4*)&A[(size_t)(bm + row) * K + kb + c4];
      *(float4*)&As[row * APITCH + c4] = tf4(v);
    }
#pragma unroll
    for (int i = 0; i < 2; i++) {
      int idx = tid + i * 256;
      int row = idx >> 5, c4 = (idx & 31) * 4;
      float4 v = *(const float4*)&B[(size_t)(kb + row) * N + bn + c4];
      *(float4*)&Bs[row * BPITCH + c4] = tf4(v);
    }
    __syncthreads();

#pragma unroll
    for (int ks = 0; ks < 2; ks++) {
      const int k0 = ks * 8;
      uint32_t af[4][4];
#pragma unroll
      for (int mt = 0; mt < 4; mt++) {
        const float* ap = &As[(wm + mt * 16) * APITCH + k0];
        af[mt][0] = fu(ap[r * APITCH + q]);
        af[mt][1] = fu(ap[(r + 8) * APITCH + q]);
        af[mt][2] = fu(ap[r * APITCH + q + 4]);
        af[mt][3] = fu(ap[(r + 8) * APITCH + q + 4]);
      }
#pragma unroll
      for (int nt = 0; nt < 4; nt++) {
        uint32_t b0 = fu(Bs[(k0 + q) * BPITCH + wn + nt * 8 + r]);
        uint32_t b1 = fu(Bs[(k0 + q + 4) * BPITCH + wn + nt * 8 + r]);
#pragma unroll
        for (int mt = 0; mt < 4; mt++)
          mma8(acc[mt][nt], af[mt][0], af[mt][1], af[mt][2], af[mt][3], b0, b1);
      }
    }
    __syncthreads();
  }

#pragma unroll
  for (int mt = 0; mt < 4; mt++) {
    int row_lo = bm + wm + mt * 16 + r;
#pragma unroll
    for (int nt = 0; nt < 4; nt++) {
      int col = bn + wn + nt * 8 + 2 * q;
      float2 bv = *(const float2*)&bias[col];
      float2 o0 = make_float2(acc[mt][nt][0] + bv.x, acc[mt][nt][1] + bv.y);
      float2 o1 = make_float2(acc[mt][nt][2] + bv.x, acc[mt][nt][3] + bv.y);
      *(float2*)&C[(size_t)row_lo * N + col] = o0;
      *(float2*)&C[(size_t)(row_lo + 8) * N + col] = o1;
    }
  }
}

// ---------------------------------------------------------------------------
// Flash attention, tf32 tensor cores. CTA = 64 queries of one (b,h), 4 warps.
// Warp w owns rows w*16..w*16+15 (one m16 band), all 64 key cols / head dims.
// Q fragments live in registers across the whole k-loop.
// ---------------------------------------------------------------------------
#define PITCH 68
#define ATT_SMEM (3 * 64 * PITCH * sizeof(float))  // Ks, Vs, Ps(=Q stage)

__global__ __launch_bounds__(128) void attn_tf32() {
  extern __shared__ float sm[];
  float* Ks = sm;
  float* Vs = sm + 64 * PITCH;
  float* Ps = sm + 2 * 64 * PITCH;  // Q staging, then P tile

  const int tid = threadIdx.x;
  const int warp = tid >> 5, lane = tid & 31;
  const int r = lane >> 2, q = lane & 3;
  const int qb = 31 - blockIdx.x;        // heavy tiles first
  const int bh = blockIdx.y;
  const int b = bh / NHEAD, h = bh % NHEAD;
  const int q0 = qb * 64;
  const float* qkv = g_qkv + (size_t)b * TSEQ * C3 + h * HDIM;

  // Stage Q (pre-scaled by 1/sqrt(D)) into Ps, rounded to tf32
  for (int i = tid; i < 64 * 16; i += 128) {
    int rr = i >> 4, d4 = (i & 15) << 2;
    float4 v = *(const float4*)&qkv[(size_t)(q0 + rr) * C3 + d4];
    v.x *= 0.125f; v.y *= 0.125f; v.z *= 0.125f; v.w *= 0.125f;
    *(float4*)&Ps[rr * PITCH + d4] = tf4(v);
  }
  __syncthreads();

  // Q fragments: 8 k-steps x 4 regs (rows warp*16 + r / +8, cols ks*8 + q / +4)
  uint32_t qf[8][4];
  const int wr = warp * 16;
#pragma unroll
  for (int ks = 0; ks < 8; ks++) {
    const float* ap = &Ps[wr * PITCH + ks * 8];
    qf[ks][0] = fu(ap[r * PITCH + q]);
    qf[ks][1] = fu(ap[(r + 8) * PITCH + q]);
    qf[ks][2] = fu(ap[r * PITCH + q + 4]);
    qf[ks][3] = fu(ap[(r + 8) * PITCH + q + 4]);
  }

  float m_lo = -1e30f, m_hi = -1e30f, l_lo = 0.0f, l_hi = 0.0f;
  float o[8][4];
#pragma unroll
  for (int nt = 0; nt < 8; nt++)
#pragma unroll
    for (int t = 0; t < 4; t++) o[nt][t] = 0.0f;

  for (int kb = 0; kb <= qb; kb++) {
    __syncthreads();  // prior iter's Ks/Vs/Ps readers done; Q-frag reads done
    for (int i = tid; i < 64 * 16; i += 128) {
      int rr = i >> 4, d4 = (i & 15) << 2;
      const float* base = &qkv[(size_t)(kb * 64 + rr) * C3 + d4];
      float4 kv = *(const float4*)(base + CEMB);
      float4 vv = *(const float4*)(base + 2 * CEMB);
      *(float4*)&Ks[rr * PITCH + d4] = tf4(kv);
      *(float4*)&Vs[rr * PITCH + d4] = tf4(vv);
    }
    __syncthreads();

    // S = Q K^T  (16 rows x 64 keys per warp)
    float s[8][4];
#pragma unroll
    for (int nt = 0; nt < 8; nt++)
#pragma unroll
      for (int t = 0; t < 4; t++) s[nt][t] = 0.0f;
#pragma unroll
    for (int ks = 0; ks < 8; ks++) {
#pragma unroll
      for (int nt = 0; nt < 8; nt++) {
        uint32_t b0 = fu(Ks[(nt * 8 + r) * PITCH + ks * 8 + q]);
        uint32_t b1 = fu(Ks[(nt * 8 + r) * PITCH + ks * 8 + q + 4]);
        mma8(s[nt], qf[ks][0], qf[ks][1], qf[ks][2], qf[ks][3], b0, b1);
      }
    }

    if (kb == qb) {  // causal mask on diagonal tile (local coords valid)
      const int row_lo = wr + r, row_hi = row_lo + 8;
#pragma unroll
      for (int nt = 0; nt < 8; nt++) {
        int col = nt * 8 + 2 * q;
        if (col > row_lo) s[nt][0] = -1e30f;
        if (col + 1 > row_lo) s[nt][1] = -1e30f;
        if (col > row_hi) s[nt][2] = -1e30f;
        if (col + 1 > row_hi) s[nt][3] = -1e30f;
      }
    }

    // Online softmax: rows (wr+r) and (wr+r+8); reduce over the 4 q-lanes
    float mx_lo = s[0][0], mx_hi = s[0][2];
#pragma unroll
    for (int nt = 0; nt < 8; nt++) {
      mx_lo = fmaxf(mx_lo, fmaxf(s[nt][0], s[nt][1]));
      mx_hi = fmaxf(mx_hi, fmaxf(s[nt][2], s[nt][3]));
    }
    mx_lo = fmaxf(mx_lo, __shfl_xor_sync(0xffffffffu, mx_lo, 1));
    mx_lo = fmaxf(mx_lo, __shfl_xor_sync(0xffffffffu, mx_lo, 2));
    mx_hi = fmaxf(mx_hi, __shfl_xor_sync(0xffffffffu, mx_hi, 1));
    mx_hi = fmaxf(mx_hi, __shfl_xor_sync(0xffffffffu, mx_hi, 2));

    float mn_lo = fmaxf(m_lo, mx_lo), mn_hi = fmaxf(m_hi, mx_hi);
    float corr_lo = __expf(m_lo - mn_lo), corr_hi = __expf(m_hi - mn_hi);

    float ls_lo = 0.0f, ls_hi = 0.0f;
#pragma unroll
    for (int nt = 0; nt < 8; nt++) {
      int col = nt * 8 + 2 * q;
      // round p to tf32 BEFORE summing so l matches the PV numerator exactly
      float p0 = __uint_as_float(f2tf(__expf(s[nt][0] - mn_lo)));
      float p1 = __uint_as_float(f2tf(__expf(s[nt][1] - mn_lo)));
      float p2 = __uint_as_float(f2tf(__expf(s[nt][2] - mn_hi)));
      float p3 = __uint_as_float(f2tf(__expf(s[nt][3] - mn_hi)));
      ls_lo += p0 + p1;
      ls_hi += p2 + p3;
      *(float2*)&Ps[(wr + r) * PITCH + col] = make_float2(p0, p1);
      *(float2*)&Ps[(wr + r + 8) * PITCH + col] = make_float2(p2, p3);
    }
    ls_lo += __shfl_xor_sync(0xffffffffu, ls_lo, 1);
    ls_lo += __shfl_xor_sync(0xffffffffu, ls_lo, 2);
    ls_hi += __shfl_xor_sync(0xffffffffu, ls_hi, 1);
    ls_hi += __shfl_xor_sync(0xffffffffu, ls_hi, 2);
    l_lo = l_lo * corr_lo + ls_lo;
    l_hi = l_hi * corr_hi + ls_hi;
    m_lo = mn_lo;
    m_hi = mn_hi;

#pragma unroll
    for (int nt = 0; nt < 8; nt++) {
      o[nt][0] *= corr_lo;
      o[nt][1] *= corr_lo;
      o[nt][2] *= corr_hi;
      o[nt][3] *= corr_hi;
    }
    __syncwarp();  // P rows are warp-private: no block sync needed

    // O += P V
#pragma unroll
    for (int ks = 0; ks < 8; ks++) {
      uint32_t a0 = fu(Ps[(wr + r) * PITCH + ks * 8 + q]);
      uint32_t a1 = fu(Ps[(wr + r + 8) * PITCH + ks * 8 + q]);
      uint32_t a2 = fu(Ps[(wr + r) * PITCH + ks * 8 + q + 4]);
      uint32_t a3 = fu(Ps[(wr + r + 8) * PITCH + ks * 8 + q + 4]);
#pragma unroll
      for (int nt = 0; nt < 8; nt++) {
        uint32_t b0 = fu(Vs[(ks * 8 + q) * PITCH + nt * 8 + r]);
        uint32_t b1 = fu(Vs[(ks * 8 + q + 4) * PITCH + nt * 8 + r]);
        mma8(o[nt], a0, a1, a2, a3, b0, b1);
      }
    }
  }

  const float il_lo = 1.0f / l_lo, il_hi = 1.0f / l_hi;
  const size_t base = ((size_t)(b * TSEQ) + q0 + wr + r) * CEMB + h * HDIM;
#pragma unroll
  for (int nt = 0; nt < 8; nt++) {
    int col = nt * 8 + 2 * q;
    *(float2*)&g_y[base + col] =
        make_float2(o[nt][0] * il_lo, o[nt][1] * il_lo);
    *(float2*)&g_y[base + 8 * CEMB + col] =
        make_float2(o[nt][2] * il_hi, o[nt][3] * il_hi);
  }
}

// ---------------------------------------------------------------------------
extern "C" void kernel_launch(void* const* d_in, const int* in_sizes, int n_in,
                              void* d_out, int out_size) {
  const float* x      = (const float*)d_in[0];
  const float* W_attn = (const float*)d_in[1];
  const float* b_attn = (const float*)d_in[2];
  const float* W_proj = (const float*)d_in[3];
  const float* b_proj = (const float*)d_in[4];
  float* out = (float*)d_out;

  float* qkv; cudaGetSymbolAddress((void**)&qkv, g_qkv);
  float* y;   cudaGetSymbolAddress((void**)&y,   g_y);

  const int M = BATCH * TSEQ;  // 4096

  gemm_tf32<<<dim3(C3 / 128, M / 128), 256>>>(x, W_attn, b_attn, qkv, C3, CEMB);

  cudaFuncSetAttribute(attn_tf32, cudaFuncAttributeMaxDynamicSharedMemorySize,
                       (int)ATT_SMEM);
  attn_tf32<<<dim3(TSEQ / 64, BATCH * NHEAD), 128, ATT_SMEM>>>();

  gemm_tf32<<<dim3(CEMB / 128, M / 128), 256>>>(y, W_proj, b_proj, out, CEMB,
                                                CEMB);
}

// round 3
// speedup vs baseline: 9.2722x; 1.1262x over previous
#include <cuda_runtime.h>
#include <stdint.h>
#include <math.h>

#define BATCH 2
#define TSEQ  2048
#define NHEAD 12
#define HDIM  64
#define CEMB  768
#define C3    (3 * CEMB)

__device__ float g_qkv[BATCH * TSEQ * C3];   // 36 MB
__device__ float g_y[BATCH * TSEQ * CEMB];   // 12 MB

__device__ __forceinline__ uint32_t f2tf(float x) {
  uint32_t r;
  asm("cvt.rna.tf32.f32 %0, %1;" : "=r"(r) : "f"(x));
  return r;
}
__device__ __forceinline__ float4 tf4(float4 v) {
  v.x = __uint_as_float(f2tf(v.x));
  v.y = __uint_as_float(f2tf(v.y));
  v.z = __uint_as_float(f2tf(v.z));
  v.w = __uint_as_float(f2tf(v.w));
  return v;
}
__device__ __forceinline__ uint32_t fu(float x) { return __float_as_uint(x); }

__device__ __forceinline__ void mma8(float* c, uint32_t a0, uint32_t a1,
                                     uint32_t a2, uint32_t a3,
                                     uint32_t b0, uint32_t b1) {
  asm volatile(
      "mma.sync.aligned.m16n8k8.row.col.f32.tf32.tf32.f32 "
      "{%0,%1,%2,%3}, {%4,%5,%6,%7}, {%8,%9}, {%0,%1,%2,%3};\n"
      : "+f"(c[0]), "+f"(c[1]), "+f"(c[2]), "+f"(c[3])
      : "r"(a0), "r"(a1), "r"(a2), "r"(a3), "r"(b0), "r"(b1));
}

// ---------------------------------------------------------------------------
// tf32 GEMM, double-buffered smem + register prefetch. 128x128 tile, BK=16,
// 256 threads, warp tile 64x32. One __syncthreads per k-step.
// ---------------------------------------------------------------------------
#define APITCH 20
#define BPITCH 132
#define ABUF (128 * APITCH)
#define BBUF (16 * BPITCH)

__global__ __launch_bounds__(256, 2) void gemm_tf32(
    const float* __restrict__ A, const float* __restrict__ B,
    const float* __restrict__ bias, float* __restrict__ C, int N, int K) {
  __shared__ float As[2 * ABUF];
  __shared__ float Bs[2 * BBUF];

  const int tid = threadIdx.x;
  const int warp = tid >> 5, lane = tid & 31;
  const int r = lane >> 2, q = lane & 3;
  const int wm = (warp >> 2) * 64, wn = (warp & 3) * 32;
  const int bm = blockIdx.y * 128, bn = blockIdx.x * 128;

  // load indices
  const int ar0 = tid >> 2, ac = (tid & 3) * 4;        // A rows ar0, ar0+64
  const int br0 = tid >> 5, bc = (tid & 31) * 4;       // B rows br0, br0+8
  const float* Ag = A + (size_t)(bm + ar0) * K + ac;
  const float* Bg = B + (size_t)br0 * N + bn + bc;

  float acc[4][4][4];
#pragma unroll
  for (int i = 0; i < 4; i++)
#pragma unroll
    for (int j = 0; j < 4; j++)
#pragma unroll
      for (int t = 0; t < 4; t++) acc[i][j][t] = 0.0f;

  const int nk = K / 16;
  float4 a0r, a1r, b0r, b1r;

  // prefetch tile 0
  a0r = *(const float4*)(Ag);
  a1r = *(const float4*)(Ag + (size_t)64 * K);
  b0r = *(const float4*)(Bg);
  b1r = *(const float4*)(Bg + (size_t)8 * N);
  {
    float* Ad = As;
    float* Bd = Bs;
    *(float4*)&Ad[ar0 * APITCH + ac] = tf4(a0r);
    *(float4*)&Ad[(ar0 + 64) * APITCH + ac] = tf4(a1r);
    *(float4*)&Bd[br0 * BPITCH + bc] = tf4(b0r);
    *(float4*)&Bd[(br0 + 8) * BPITCH + bc] = tf4(b1r);
  }
  __syncthreads();

  for (int kb = 0; kb < nk; kb++) {
    const int cur = kb & 1;
    // prefetch next tile into regs (latency covered by compute below)
    if (kb + 1 < nk) {
      const float* Agn = Ag + (kb + 1) * 16;
      const float* Bgn = Bg + (size_t)(kb + 1) * 16 * N;
      a0r = *(const float4*)(Agn);
      a1r = *(const float4*)(Agn + (size_t)64 * K);
      b0r = *(const float4*)(Bgn);
      b1r = *(const float4*)(Bgn + (size_t)8 * N);
    }

    const float* Ac = As + cur * ABUF;
    const float* Bc = Bs + cur * BBUF;
#pragma unroll
    for (int ks = 0; ks < 2; ks++) {
      const int k0 = ks * 8;
      uint32_t af[4][4];
#pragma unroll
      for (int mt = 0; mt < 4; mt++) {
        const float* ap = &Ac[(wm + mt * 16) * APITCH + k0];
        af[mt][0] = fu(ap[r * APITCH + q]);
        af[mt][1] = fu(ap[(r + 8) * APITCH + q]);
        af[mt][2] = fu(ap[r * APITCH + q + 4]);
        af[mt][3] = fu(ap[(r + 8) * APITCH + q + 4]);
      }
#pragma unroll
      for (int nt = 0; nt < 4; nt++) {
        uint32_t b0 = fu(Bc[(k0 + q) * BPITCH + wn + nt * 8 + r]);
        uint32_t b1 = fu(Bc[(k0 + q + 4) * BPITCH + wn + nt * 8 + r]);
#pragma unroll
        for (int mt = 0; mt < 4; mt++)
          mma8(acc[mt][nt], af[mt][0], af[mt][1], af[mt][2], af[mt][3], b0, b1);
      }
    }

    if (kb + 1 < nk) {
      float* Ad = As + (cur ^ 1) * ABUF;
      float* Bd = Bs + (cur ^ 1) * BBUF;
      *(float4*)&Ad[ar0 * APITCH + ac] = tf4(a0r);
      *(float4*)&Ad[(ar0 + 64) * APITCH + ac] = tf4(a1r);
      *(float4*)&Bd[br0 * BPITCH + bc] = tf4(b0r);
      *(float4*)&Bd[(br0 + 8) * BPITCH + bc] = tf4(b1r);
    }
    __syncthreads();
  }

#pragma unroll
  for (int mt = 0; mt < 4; mt++) {
    int row_lo = bm + wm + mt * 16 + r;
#pragma unroll
    for (int nt = 0; nt < 4; nt++) {
      int col = bn + wn + nt * 8 + 2 * q;
      float2 bv = *(const float2*)&bias[col];
      *(float2*)&C[(size_t)row_lo * N + col] =
          make_float2(acc[mt][nt][0] + bv.x, acc[mt][nt][1] + bv.y);
      *(float2*)&C[(size_t)(row_lo + 8) * N + col] =
          make_float2(acc[mt][nt][2] + bv.x, acc[mt][nt][3] + bv.y);
    }
  }
}

// ---------------------------------------------------------------------------
// Flash attention, tf32 mma, fully pipelined global loads.
// CTA = 64 queries of one (b,h), 4 warps, warp owns a 16-row band.
// K tile prefetched one iter ahead (regs); V LDG issued before sync#1 and
// stored to smem only after S-mma/softmax — no exposed global latency.
// ---------------------------------------------------------------------------
#define PITCH 68
#define ATT_SMEM (3 * 64 * PITCH * sizeof(float))  // Ks, Vs, Ps(Q stage)

__global__ __launch_bounds__(128, 2) void attn_tf32() {
  extern __shared__ float sm[];
  float* Ks = sm;
  float* Vs = sm + 64 * PITCH;
  float* Ps = sm + 2 * 64 * PITCH;

  const int tid = threadIdx.x;
  const int warp = tid >> 5, lane = tid & 31;
  const int r = lane >> 2, q = lane & 3;
  const int qb = 31 - blockIdx.x;  // heavy tiles first
  const int bh = blockIdx.y;
  const int b = bh / NHEAD, h = bh % NHEAD;
  const int q0 = qb * 64;
  const float* qkv = g_qkv + (size_t)b * TSEQ * C3 + h * HDIM;

  // per-thread load geometry: 8 float4 per tile, rows rbase + 8j, col d4
  const int rbase = tid >> 4;
  const int d4 = (tid & 15) << 2;

  // Stage Q (pre-scaled) into Ps
#pragma unroll
  for (int j = 0; j < 8; j++) {
    int rr = rbase + j * 8;
    float4 v = *(const float4*)&qkv[(size_t)(q0 + rr) * C3 + d4];
    v.x *= 0.125f; v.y *= 0.125f; v.z *= 0.125f; v.w *= 0.125f;
    *(float4*)&Ps[rr * PITCH + d4] = tf4(v);
  }
  __syncthreads();

  uint32_t qf[8][4];
  const int wr = warp * 16;
#pragma unroll
  for (int ks = 0; ks < 8; ks++) {
    const float* ap = &Ps[wr * PITCH + ks * 8];
    qf[ks][0] = fu(ap[r * PITCH + q]);
    qf[ks][1] = fu(ap[(r + 8) * PITCH + q]);
    qf[ks][2] = fu(ap[r * PITCH + q + 4]);
    qf[ks][3] = fu(ap[(r + 8) * PITCH + q + 4]);
  }

  float m_lo = -1e30f, m_hi = -1e30f, l_lo = 0.0f, l_hi = 0.0f;
  float o[8][4];
#pragma unroll
  for (int nt = 0; nt < 8; nt++)
#pragma unroll
    for (int t = 0; t < 4; t++) o[nt][t] = 0.0f;

  float4 kreg[8], vreg[8];
  // prefetch K tile 0
#pragma unroll
  for (int j = 0; j < 8; j++)
    kreg[j] = *(const float4*)&qkv[(size_t)(rbase + j * 8) * C3 + CEMB + d4];

  __syncthreads();  // Q frag reads done before Ps is reused for P

  for (int kb = 0; kb <= qb; kb++) {
    // store prefetched K (cvt at store); regs then reused for next prefetch
#pragma unroll
    for (int j = 0; j < 8; j++)
      *(float4*)&Ks[(rbase + j * 8) * PITCH + d4] = tf4(kreg[j]);

    if (kb < qb) {
      const float* nb = &qkv[(size_t)((kb + 1) * 64 + rbase) * C3 + CEMB + d4];
#pragma unroll
      for (int j = 0; j < 8; j++) kreg[j] = *(const float4*)(nb + (size_t)j * 8 * C3);
    }
    {
      const float* vb = &qkv[(size_t)(kb * 64 + rbase) * C3 + 2 * CEMB + d4];
#pragma unroll
      for (int j = 0; j < 8; j++) vreg[j] = *(const float4*)(vb + (size_t)j * 8 * C3);
    }
    __syncthreads();  // Ks visible (also: prev iter PV readers of Vs/Ps done)

    // S = Q K^T
    float s[8][4];
#pragma unroll
    for (int nt = 0; nt < 8; nt++)
#pragma unroll
      for (int t = 0; t < 4; t++) s[nt][t] = 0.0f;
#pragma unroll
    for (int ks = 0; ks < 8; ks++) {
#pragma unroll
      for (int nt = 0; nt < 8; nt++) {
        uint32_t b0 = fu(Ks[(nt * 8 + r) * PITCH + ks * 8 + q]);
        uint32_t b1 = fu(Ks[(nt * 8 + r) * PITCH + ks * 8 + q + 4]);
        mma8(s[nt], qf[ks][0], qf[ks][1], qf[ks][2], qf[ks][3], b0, b1);
      }
    }

    if (kb == qb) {
      const int row_lo = wr + r, row_hi = row_lo + 8;
#pragma unroll
      for (int nt = 0; nt < 8; nt++) {
        int col = nt * 8 + 2 * q;
        if (col > row_lo) s[nt][0] = -1e30f;
        if (col + 1 > row_lo) s[nt][1] = -1e30f;
        if (col > row_hi) s[nt][2] = -1e30f;
        if (col + 1 > row_hi) s[nt][3] = -1e30f;
      }
    }

    float mx_lo = s[0][0], mx_hi = s[0][2];
#pragma unroll
    for (int nt = 0; nt < 8; nt++) {
      mx_lo = fmaxf(mx_lo, fmaxf(s[nt][0], s[nt][1]));
      mx_hi = fmaxf(mx_hi, fmaxf(s[nt][2], s[nt][3]));
    }
    mx_lo = fmaxf(mx_lo, __shfl_xor_sync(0xffffffffu, mx_lo, 1));
    mx_lo = fmaxf(mx_lo, __shfl_xor_sync(0xffffffffu, mx_lo, 2));
    mx_hi = fmaxf(mx_hi, __shfl_xor_sync(0xffffffffu, mx_hi, 1));
    mx_hi = fmaxf(mx_hi, __shfl_xor_sync(0xffffffffu, mx_hi, 2));

    float mn_lo = fmaxf(m_lo, mx_lo), mn_hi = fmaxf(m_hi, mx_hi);
    float corr_lo = __expf(m_lo - mn_lo), corr_hi = __expf(m_hi - mn_hi);

    float ls_lo = 0.0f, ls_hi = 0.0f;
#pragma unroll
    for (int nt = 0; nt < 8; nt++) {
      int col = nt * 8 + 2 * q;
      float p0 = __uint_as_float(f2tf(__expf(s[nt][0] - mn_lo)));
      float p1 = __uint_as_float(f2tf(__expf(s[nt][1] - mn_lo)));
      float p2 = __uint_as_float(f2tf(__expf(s[nt][2] - mn_hi)));
      float p3 = __uint_as_float(f2tf(__expf(s[nt][3] - mn_hi)));
      ls_lo += p0 + p1;
      ls_hi += p2 + p3;
      *(float2*)&Ps[(wr + r) * PITCH + col] = make_float2(p0, p1);
      *(float2*)&Ps[(wr + r + 8) * PITCH + col] = make_float2(p2, p3);
    }
    ls_lo += __shfl_xor_sync(0xffffffffu, ls_lo, 1);
    ls_lo += __shfl_xor_sync(0xffffffffu, ls_lo, 2);
    ls_hi += __shfl_xor_sync(0xffffffffu, ls_hi, 1);
    ls_hi += __shfl_xor_sync(0xffffffffu, ls_hi, 2);
    l_lo = l_lo * corr_lo + ls_lo;
    l_hi = l_hi * corr_hi + ls_hi;
    m_lo = mn_lo;
    m_hi = mn_hi;

#pragma unroll
    for (int nt = 0; nt < 8; nt++) {
      o[nt][0] *= corr_lo;
      o[nt][1] *= corr_lo;
      o[nt][2] *= corr_hi;
      o[nt][3] *= corr_hi;
    }

    // store V (its LDG latency was covered by S-mma + softmax above)
#pragma unroll
    for (int j = 0; j < 8; j++)
      *(float4*)&Vs[(rbase + j * 8) * PITCH + d4] = tf4(vreg[j]);
    __syncthreads();  // Vs visible (Ps rows are warp-private)

    // O += P V
#pragma unroll
    for (int ks = 0; ks < 8; ks++) {
      uint32_t a0 = fu(Ps[(wr + r) * PITCH + ks * 8 + q]);
      uint32_t a1 = fu(Ps[(wr + r + 8) * PITCH + ks * 8 + q]);
      uint32_t a2 = fu(Ps[(wr + r) * PITCH + ks * 8 + q + 4]);
      uint32_t a3 = fu(Ps[(wr + r + 8) * PITCH + ks * 8 + q + 4]);
#pragma unroll
      for (int nt = 0; nt < 8; nt++) {
        uint32_t b0 = fu(Vs[(ks * 8 + q) * PITCH + nt * 8 + r]);
        uint32_t b1 = fu(Vs[(ks * 8 + q + 4) * PITCH + nt * 8 + r]);
        mma8(o[nt], a0, a1, a2, a3, b0, b1);
      }
    }
  }

  const float il_lo = 1.0f / l_lo, il_hi = 1.0f / l_hi;
  const size_t base = ((size_t)(b * TSEQ) + q0 + wr + r) * CEMB + h * HDIM;
#pragma unroll
  for (int nt = 0; nt < 8; nt++) {
    int col = nt * 8 + 2 * q;
    *(float2*)&g_y[base + col] =
        make_float2(o[nt][0] * il_lo, o[nt][1] * il_lo);
    *(float2*)&g_y[base + 8 * CEMB + col] =
        make_float2(o[nt][2] * il_hi, o[nt][3] * il_hi);
  }
}

// ---------------------------------------------------------------------------
extern "C" void kernel_launch(void* const* d_in, const int* in_sizes, int n_in,
                              void* d_out, int out_size) {
  const float* x      = (const float*)d_in[0];
  const float* W_attn = (const float*)d_in[1];
  const float* b_attn = (const float*)d_in[2];
  const float* W_proj = (const float*)d_in[3];
  const float* b_proj = (const float*)d_in[4];
  float* out = (float*)d_out;

  float* qkv; cudaGetSymbolAddress((void**)&qkv, g_qkv);
  float* y;   cudaGetSymbolAddress((void**)&y,   g_y);

  const int M = BATCH * TSEQ;  // 4096

  gemm_tf32<<<dim3(C3 / 128, M / 128), 256>>>(x, W_attn, b_attn, qkv, C3, CEMB);

  cudaFuncSetAttribute(attn_tf32, cudaFuncAttributeMaxDynamicSharedMemorySize,
                       (int)ATT_SMEM);
  attn_tf32<<<dim3(TSEQ / 64, BATCH * NHEAD), 128, ATT_SMEM>>>();

  gemm_tf32<<<dim3(CEMB / 128, M / 128), 256>>>(y, W_proj, b_proj, out, CEMB,
                                                CEMB);
}

// round 5
// speedup vs baseline: 10.3322x; 1.1143x over previous
#include <cuda_runtime.h>
#include <stdint.h>
#include <math.h>

#define BATCH 2
#define TSEQ  2048
#define NHEAD 12
#define HDIM  64
#define CEMB  768
#define C3    (3 * CEMB)

__device__ float g_qkv[BATCH * TSEQ * C3];    // 36 MB (tf32-rounded values)
__device__ float g_y[BATCH * TSEQ * CEMB];    // 12 MB (tf32-rounded values)
__device__ float g_xr[BATCH * TSEQ * CEMB];   // 12 MB rounded x
__device__ float g_war[CEMB * C3];            // 7 MB rounded W_attn
__device__ float g_wpr[CEMB * CEMB];          // 2.25 MB rounded W_proj

__device__ __forceinline__ uint32_t f2tf(float x) {
  uint32_t r;
  asm("cvt.rna.tf32.f32 %0, %1;" : "=r"(r) : "f"(x));
  return r;
}
__device__ __forceinline__ float4 tf4(float4 v) {
  v.x = __uint_as_float(f2tf(v.x));
  v.y = __uint_as_float(f2tf(v.y));
  v.z = __uint_as_float(f2tf(v.z));
  v.w = __uint_as_float(f2tf(v.w));
  return v;
}
__device__ __forceinline__ uint32_t fu(float x) { return __float_as_uint(x); }

__device__ __forceinline__ void mma8(float* c, uint32_t a0, uint32_t a1,
                                     uint32_t a2, uint32_t a3,
                                     uint32_t b0, uint32_t b1) {
  asm volatile(
      "mma.sync.aligned.m16n8k8.row.col.f32.tf32.tf32.f32 "
      "{%0,%1,%2,%3}, {%4,%5,%6,%7}, {%8,%9}, {%0,%1,%2,%3};\n"
      : "+f"(c[0]), "+f"(c[1]), "+f"(c[2]), "+f"(c[3])
      : "r"(a0), "r"(a1), "r"(a2), "r"(a3), "r"(b0), "r"(b1));
}

__device__ __forceinline__ void cpa16(void* s, const void* g) {
  uint32_t sa = (uint32_t)__cvta_generic_to_shared(s);
  asm volatile("cp.async.cg.shared.global [%0], [%1], 16;\n" ::"r"(sa), "l"(g));
}
#define CP_COMMIT() asm volatile("cp.async.commit_group;\n")
#define CP_WAIT(n)  asm volatile("cp.async.wait_group %0;\n" ::"n"(n))

// ---------------------------------------------------------------------------
// Elementwise rna-round to tf32 (pre-pass; memory-bound, ~µs)
// ---------------------------------------------------------------------------
__global__ __launch_bounds__(256) void round_tf32(const float* __restrict__ in,
                                                  float* __restrict__ out,
                                                  int n4) {
  int i = blockIdx.x * 256 + threadIdx.x;
  if (i < n4) *(float4*)&out[i * 4] = tf4(*(const float4*)&in[i * 4]);
}

// ---------------------------------------------------------------------------
// tf32 GEMM, 4-stage cp.async pipeline. Operands pre-rounded -> no CVT in
// the hot loop. 128x128 tile, BK=16, 256 threads, warp tile 64x32.
// ROUND_OUT: round the (acc+bias) result to tf32 at the epilogue.
// ---------------------------------------------------------------------------
#define APITCH 20
#define BPITCH 132
#define ABUF (128 * APITCH)
#define BBUF (16 * BPITCH)
#define GSTAGES 4
#define GEMM_SMEM (GSTAGES * (ABUF + BBUF) * sizeof(float))

template <bool ROUND_OUT>
__global__ __launch_bounds__(256, 2) void gemm_tf32(
    const float* __restrict__ A, const float* __restrict__ B,
    const float* __restrict__ bias, float* __restrict__ C, int N, int K) {
  extern __shared__ float sm[];
  float* As = sm;
  float* Bs = sm + GSTAGES * ABUF;

  const int tid = threadIdx.x;
  const int warp = tid >> 5, lane = tid & 31;
  const int r = lane >> 2, q = lane & 3;
  const int wm = (warp >> 2) * 64, wn = (warp & 3) * 32;
  const int bm = blockIdx.y * 128, bn = blockIdx.x * 128;

  const int ar0 = tid >> 2, ac = (tid & 3) * 4;
  const int br0 = tid >> 5, bc = (tid & 31) * 4;
  const float* Ag = A + (size_t)(bm + ar0) * K + ac;
  const float* Bg = B + (size_t)br0 * N + bn + bc;

  float acc[4][4][4];
#pragma unroll
  for (int i = 0; i < 4; i++)
#pragma unroll
    for (int j = 0; j < 4; j++)
#pragma unroll
      for (int t = 0; t < 4; t++) acc[i][j][t] = 0.0f;

  const int nk = K / 16;

#pragma unroll
  for (int i = 0; i < GSTAGES - 1; i++) {
    if (i < nk) {
      float* Ad = As + i * ABUF;
      float* Bd = Bs + i * BBUF;
      const float* Agk = Ag + i * 16;
      const float* Bgk = Bg + (size_t)i * 16 * N;
      cpa16(&Ad[ar0 * APITCH + ac], Agk);
      cpa16(&Ad[(ar0 + 64) * APITCH + ac], Agk + (size_t)64 * K);
      cpa16(&Bd[br0 * BPITCH + bc], Bgk);
      cpa16(&Bd[(br0 + 8) * BPITCH + bc], Bgk + (size_t)8 * N);
    }
    CP_COMMIT();
  }
  CP_WAIT(2);
  __syncthreads();

  for (int kb = 0; kb < nk; kb++) {
    const float* Ac = As + (kb & 3) * ABUF;
    const float* Bc = Bs + (kb & 3) * BBUF;
#pragma unroll
    for (int ks = 0; ks < 2; ks++) {
      const int k0 = ks * 8;
      uint32_t af[4][4];
#pragma unroll
      for (int mt = 0; mt < 4; mt++) {
        const float* ap = &Ac[(wm + mt * 16) * APITCH + k0];
        af[mt][0] = fu(ap[r * APITCH + q]);
        af[mt][1] = fu(ap[(r + 8) * APITCH + q]);
        af[mt][2] = fu(ap[r * APITCH + q + 4]);
        af[mt][3] = fu(ap[(r + 8) * APITCH + q + 4]);
      }
#pragma unroll
      for (int nt = 0; nt < 4; nt++) {
        uint32_t b0 = fu(Bc[(k0 + q) * BPITCH + wn + nt * 8 + r]);
        uint32_t b1 = fu(Bc[(k0 + q + 4) * BPITCH + wn + nt * 8 + r]);
#pragma unroll
        for (int mt = 0; mt < 4; mt++)
          mma8(acc[mt][nt], af[mt][0], af[mt][1], af[mt][2], af[mt][3], b0, b1);
      }
    }

    if (kb + 3 < nk) {
      int st = (kb + 3) & 3;
      float* Ad = As + st * ABUF;
      float* Bd = Bs + st * BBUF;
      const float* Agk = Ag + (kb + 3) * 16;
      const float* Bgk = Bg + (size_t)(kb + 3) * 16 * N;
      cpa16(&Ad[ar0 * APITCH + ac], Agk);
      cpa16(&Ad[(ar0 + 64) * APITCH + ac], Agk + (size_t)64 * K);
      cpa16(&Bd[br0 * BPITCH + bc], Bgk);
      cpa16(&Bd[(br0 + 8) * BPITCH + bc], Bgk + (size_t)8 * N);
    }
    CP_COMMIT();
    CP_WAIT(2);
    __syncthreads();
  }

#pragma unroll
  for (int mt = 0; mt < 4; mt++) {
    int row_lo = bm + wm + mt * 16 + r;
#pragma unroll
    for (int nt = 0; nt < 4; nt++) {
      int col = bn + wn + nt * 8 + 2 * q;
      float2 bv = *(const float2*)&bias[col];
      float2 o0 = make_float2(acc[mt][nt][0] + bv.x, acc[mt][nt][1] + bv.y);
      float2 o1 = make_float2(acc[mt][nt][2] + bv.x, acc[mt][nt][3] + bv.y);
      if (ROUND_OUT) {
        o0.x = __uint_as_float(f2tf(o0.x));
        o0.y = __uint_as_float(f2tf(o0.y));
        o1.x = __uint_as_float(f2tf(o1.x));
        o1.y = __uint_as_float(f2tf(o1.y));
      }
      *(float2*)&C[(size_t)row_lo * N + col] = o0;
      *(float2*)&C[(size_t)(row_lo + 8) * N + col] = o1;
    }
  }
}

// ---------------------------------------------------------------------------
// Flash attention, tf32 mma, cp.async pipelined, 3 CTAs/SM.
// qkv values are already tf32-representable -> raw cp.async, no CVT.
// K double-buffered (1 tile ahead), V single-buffered.
// ---------------------------------------------------------------------------
#define PITCH 68
#define ATT_SMEM (4 * 64 * PITCH * sizeof(float))  // K0, K1, V, Ps

__global__ __launch_bounds__(128, 3) void attn_tf32() {
  extern __shared__ float sm[];
  float* Kb0 = sm;
  float* Kb1 = sm + 64 * PITCH;
  float* Vs  = sm + 2 * 64 * PITCH;
  float* Ps  = sm + 3 * 64 * PITCH;

  const int tid = threadIdx.x;
  const int warp = tid >> 5, lane = tid & 31;
  const int r = lane >> 2, q = lane & 3;
  const int qb = 31 - blockIdx.x;
  const int bh = blockIdx.y;
  const int b = bh / NHEAD, h = bh % NHEAD;
  const int q0 = qb * 64;
  const float* qkv = g_qkv + (size_t)b * TSEQ * C3 + h * HDIM;

  const int rbase = tid >> 4;
  const int d4 = (tid & 15) << 2;

  // Stage Q (scale by 1/8 is exact for tf32 values) into Ps
#pragma unroll
  for (int j = 0; j < 8; j++) {
    int rr = rbase + j * 8;
    float4 v = *(const float4*)&qkv[(size_t)(q0 + rr) * C3 + d4];
    v.x *= 0.125f; v.y *= 0.125f; v.z *= 0.125f; v.w *= 0.125f;
    *(float4*)&Ps[rr * PITCH + d4] = v;
  }
  {
    const float* kg = &qkv[(size_t)rbase * C3 + CEMB + d4];
#pragma unroll
    for (int j = 0; j < 8; j++)
      cpa16(&Kb0[(rbase + j * 8) * PITCH + d4], kg + (size_t)j * 8 * C3);
    CP_COMMIT();
  }
  __syncthreads();

  uint32_t qf[8][4];
  const int wr = warp * 16;
#pragma unroll
  for (int ks = 0; ks < 8; ks++) {
    const float* ap = &Ps[wr * PITCH + ks * 8];
    qf[ks][0] = fu(ap[r * PITCH + q]);
    qf[ks][1] = fu(ap[(r + 8) * PITCH + q]);
    qf[ks][2] = fu(ap[r * PITCH + q + 4]);
    qf[ks][3] = fu(ap[(r + 8) * PITCH + q + 4]);
  }
  __syncthreads();

  float m_lo = -1e30f, m_hi = -1e30f, l_lo = 0.0f, l_hi = 0.0f;
  float o[8][4];
#pragma unroll
  for (int nt = 0; nt < 8; nt++)
#pragma unroll
    for (int t = 0; t < 4; t++) o[nt][t] = 0.0f;

  for (int kb = 0; kb <= qb; kb++) {
    {
      const float* vg = &qkv[(size_t)(kb * 64 + rbase) * C3 + 2 * CEMB + d4];
#pragma unroll
      for (int j = 0; j < 8; j++)
        cpa16(&Vs[(rbase + j * 8) * PITCH + d4], vg + (size_t)j * 8 * C3);
      CP_COMMIT();
    }
    if (kb < qb) {
      float* Kn = (kb & 1) ? Kb0 : Kb1;
      const float* kg = &qkv[(size_t)((kb + 1) * 64 + rbase) * C3 + CEMB + d4];
#pragma unroll
      for (int j = 0; j < 8; j++)
        cpa16(&Kn[(rbase + j * 8) * PITCH + d4], kg + (size_t)j * 8 * C3);
    }
    CP_COMMIT();

    CP_WAIT(2);
    __syncthreads();

    const float* Kc = (kb & 1) ? Kb1 : Kb0;

    float s[8][4];
#pragma unroll
    for (int nt = 0; nt < 8; nt++)
#pragma unroll
      for (int t = 0; t < 4; t++) s[nt][t] = 0.0f;
#pragma unroll
    for (int ks = 0; ks < 8; ks++) {
#pragma unroll
      for (int nt = 0; nt < 8; nt++) {
        uint32_t b0 = fu(Kc[(nt * 8 + r) * PITCH + ks * 8 + q]);
        uint32_t b1 = fu(Kc[(nt * 8 + r) * PITCH + ks * 8 + q + 4]);
        mma8(s[nt], qf[ks][0], qf[ks][1], qf[ks][2], qf[ks][3], b0, b1);
      }
    }

    if (kb == qb) {
      const int row_lo = wr + r, row_hi = row_lo + 8;
#pragma unroll
      for (int nt = 0; nt < 8; nt++) {
        int col = nt * 8 + 2 * q;
        if (col > row_lo) s[nt][0] = -1e30f;
        if (col + 1 > row_lo) s[nt][1] = -1e30f;
        if (col > row_hi) s[nt][2] = -1e30f;
        if (col + 1 > row_hi) s[nt][3] = -1e30f;
      }
    }

    float mx_lo = s[0][0], mx_hi = s[0][2];
#pragma unroll
    for (int nt = 0; nt < 8; nt++) {
      mx_lo = fmaxf(mx_lo, fmaxf(s[nt][0], s[nt][1]));
      mx_hi = fmaxf(mx_hi, fmaxf(s[nt][2], s[nt][3]));
    }
    mx_lo = fmaxf(mx_lo, __shfl_xor_sync(0xffffffffu, mx_lo, 1));
    mx_lo = fmaxf(mx_lo, __shfl_xor_sync(0xffffffffu, mx_lo, 2));
    mx_hi = fmaxf(mx_hi, __shfl_xor_sync(0xffffffffu, mx_hi, 1));
    mx_hi = fmaxf(mx_hi, __shfl_xor_sync(0xffffffffu, mx_hi, 2));

    float mn_lo = fmaxf(m_lo, mx_lo), mn_hi = fmaxf(m_hi, mx_hi);
    float corr_lo = __expf(m_lo - mn_lo), corr_hi = __expf(m_hi - mn_hi);

    float ls_lo = 0.0f, ls_hi = 0.0f;
#pragma unroll
    for (int nt = 0; nt < 8; nt++) {
      int col = nt * 8 + 2 * q;
      float p0 = __uint_as_float(f2tf(__expf(s[nt][0] - mn_lo)));
      float p1 = __uint_as_float(f2tf(__expf(s[nt][1] - mn_lo)));
      float p2 = __uint_as_float(f2tf(__expf(s[nt][2] - mn_hi)));
      float p3 = __uint_as_float(f2tf(__expf(s[nt][3] - mn_hi)));
      ls_lo += p0 + p1;
      ls_hi += p2 + p3;
      *(float2*)&Ps[(wr + r) * PITCH + col] = make_float2(p0, p1);
      *(float2*)&Ps[(wr + r + 8) * PITCH + col] = make_float2(p2, p3);
    }
    ls_lo += __shfl_xor_sync(0xffffffffu, ls_lo, 1);
    ls_lo += __shfl_xor_sync(0xffffffffu, ls_lo, 2);
    ls_hi += __shfl_xor_sync(0xffffffffu, ls_hi, 1);
    ls_hi += __shfl_xor_sync(0xffffffffu, ls_hi, 2);
    l_lo = l_lo * corr_lo + ls_lo;
    l_hi = l_hi * corr_hi + ls_hi;
    m_lo = mn_lo;
    m_hi = mn_hi;

#pragma unroll
    for (int nt = 0; nt < 8; nt++) {
      o[nt][0] *= corr_lo;
      o[nt][1] *= corr_lo;
      o[nt][2] *= corr_hi;
      o[nt][3] *= corr_hi;
    }

    CP_WAIT(1);
    __syncthreads();

#pragma unroll
    for (int ks = 0; ks < 8; ks++) {
      uint32_t a0 = fu(Ps[(wr + r) * PITCH + ks * 8 + q]);
      uint32_t a1 = fu(Ps[(wr + r + 8) * PITCH + ks * 8 + q]);
      uint32_t a2 = fu(Ps[(wr + r) * PITCH + ks * 8 + q + 4]);
      uint32_t a3 = fu(Ps[(wr + r + 8) * PITCH + ks * 8 + q + 4]);
#pragma unroll
      for (int nt = 0; nt < 8; nt++) {
        uint32_t b0 = fu(Vs[(ks * 8 + q) * PITCH + nt * 8 + r]);
        uint32_t b1 = fu(Vs[(ks * 8 + q + 4) * PITCH + nt * 8 + r]);
        mma8(o[nt], a0, a1, a2, a3, b0, b1);
      }
    }
    __syncthreads();
  }

  // epilogue: divide, round to tf32 (y feeds the proj gemm raw)
  const float il_lo = 1.0f / l_lo, il_hi = 1.0f / l_hi;
  const size_t base = ((size_t)(b * TSEQ) + q0 + wr + r) * CEMB + h * HDIM;
#pragma unroll
  for (int nt = 0; nt < 8; nt++) {
    int col = nt * 8 + 2 * q;
    float2 y0 = make_float2(o[nt][0] * il_lo, o[nt][1] * il_lo);
    float2 y1 = make_float2(o[nt][2] * il_hi, o[nt][3] * il_hi);
    y0.x = __uint_as_float(f2tf(y0.x));
    y0.y = __uint_as_float(f2tf(y0.y));
    y1.x = __uint_as_float(f2tf(y1.x));
    y1.y = __uint_as_float(f2tf(y1.y));
    *(float2*)&g_y[base + col] = y0;
    *(float2*)&g_y[base + 8 * CEMB + col] = y1;
  }
}

// ---------------------------------------------------------------------------
extern "C" void kernel_launch(void* const* d_in, const int* in_sizes, int n_in,
                              void* d_out, int out_size) {
  const float* x      = (const float*)d_in[0];
  const float* W_attn = (const float*)d_in[1];
  const float* b_attn = (const float*)d_in[2];
  const float* W_proj = (const float*)d_in[3];
  const float* b_proj = (const float*)d_in[4];
  float* out = (float*)d_out;

  float* qkv; cudaGetSymbolAddress((void**)&qkv, g_qkv);
  float* y;   cudaGetSymbolAddress((void**)&y,   g_y);
  float* xr;  cudaGetSymbolAddress((void**)&xr,  g_xr);
  float* war; cudaGetSymbolAddress((void**)&war, g_war);
  float* wpr; cudaGetSymbolAddress((void**)&wpr, g_wpr);

  const int M = BATCH * TSEQ;  // 4096

  cudaFuncSetAttribute(gemm_tf32<true>,
                       cudaFuncAttributeMaxDynamicSharedMemorySize,
                       (int)GEMM_SMEM);
  cudaFuncSetAttribute(gemm_tf32<false>,
                       cudaFuncAttributeMaxDynamicSharedMemorySize,
                       (int)GEMM_SMEM);
  cudaFuncSetAttribute(attn_tf32, cudaFuncAttributeMaxDynamicSharedMemorySize,
                       (int)ATT_SMEM);

  // pre-round inputs to tf32 (rna) so the GEMM hot loop needs no CVT
  {
    int n4;
    n4 = (M * CEMB) / 4;
    round_tf32<<<(n4 + 255) / 256, 256>>>(x, xr, n4);
    n4 = (CEMB * C3) / 4;
    round_tf32<<<(n4 + 255) / 256, 256>>>(W_attn, war, n4);
    n4 = (CEMB * CEMB) / 4;
    round_tf32<<<(n4 + 255) / 256, 256>>>(W_proj, wpr, n4);
  }

  gemm_tf32<true><<<dim3(C3 / 128, M / 128), 256, GEMM_SMEM>>>(
      xr, war, b_attn, qkv, C3, CEMB);

  attn_tf32<<<dim3(TSEQ / 64, BATCH * NHEAD), 128, ATT_SMEM>>>();

  gemm_tf32<false><<<dim3(CEMB / 128, M / 128), 256, GEMM_SMEM>>>(
      y, wpr, b_proj, out, CEMB, CEMB);
}